// round 11
// baseline (speedup 1.0000x reference)
#include <cuda_runtime.h>
#include <cuda_fp16.h>

// GRU: B=64, T=1024, INPUT=512, HIDDEN=1024
// out = (B,T,H) fp32 followed by h_n = (1,B,H) fp32.

#define Bdim 64
#define Tdim 1024
#define Idim 512
#define Hdim 1024
#define NCTA 64
#define BH   (Bdim * Hdim)

// ------------------------- device scratch (static; no runtime alloc) -------
static __device__ float g_xg[3ull * Tdim * Bdim * Hdim];  // [gate][t][b][h], bias included
// Double-buffered fragment-ordered fp16 state (granule (K,s): 32 lanes x 16B):
static __device__ uint4 g_h16 [2][64 * 4 * 32];   // h   as mma-A fragments
static __device__ uint4 g_rh16[2][64 * 4 * 32];   // r*h as mma-A fragments
static __device__ unsigned g_flagA[NCTA];         // rh published (monotonic token)
static __device__ unsigned g_flagH[NCTA];         // h  published (monotonic token)

__device__ __forceinline__ unsigned packh2(float a, float b) {
    __half2 h = __floats2half2_rn(a, b);
    return *reinterpret_cast<unsigned*>(&h);
}
__device__ __forceinline__ float sigf(float x) { return 1.0f / (1.0f + __expf(-x)); }

__device__ __forceinline__ unsigned ldacq(const unsigned* p) {
    unsigned v;
    asm volatile("ld.acquire.gpu.global.u32 %0, [%1];" : "=r"(v) : "l"(p));
    return v;
}
__device__ __forceinline__ void strel(unsigned* p, unsigned v) {
    asm volatile("st.release.gpu.global.u32 [%0], %1;" :: "l"(p), "r"(v));
}
// Warp waits until the 16 producer CTAs of k-quarter kq have published >= target.
__device__ __forceinline__ void warp_wait(const unsigned* flags, int kq, unsigned target, int lane) {
    if (lane < 16) {
        const unsigned* f = flags + kq * 16 + lane;
        while ((int)(ldacq(f) - target) < 0) __nanosleep(40);
    }
    __syncwarp();
}

// D += A(16x16,row) * B(16x8,col)  fp16 -> fp32
__device__ __forceinline__ void mma16(float* d, const uint4 a, const uint2 b) {
    asm volatile(
        "mma.sync.aligned.m16n8k16.row.col.f32.f16.f16.f32 "
        "{%0,%1,%2,%3}, {%4,%5,%6,%7}, {%8,%9}, {%0,%1,%2,%3};\n"
        : "+f"(d[0]), "+f"(d[1]), "+f"(d[2]), "+f"(d[3])
        : "r"(a.x), "r"(a.y), "r"(a.z), "r"(a.w), "r"(b.x), "r"(b.y));
}

// 16-step k-quarter GEMM, 4 accumulators (z0,z1,r0,r1) sharing one A-stream.
__device__ __forceinline__ void kloop4(const uint4* __restrict__ Ag,
                                       const uint2* __restrict__ Wz0,
                                       const uint2* __restrict__ Wr0,
                                       float* z0, float* z1, float* r0, float* r1) {
    uint4 abuf[4];
    #pragma unroll
    for (int i = 0; i < 4; i++) abuf[i] = __ldcg(Ag + i * 128);
    #pragma unroll
    for (int kk = 0; kk < 16; kk++) {
        uint4 av = abuf[kk & 3];
        if (kk < 12) abuf[kk & 3] = __ldcg(Ag + (kk + 4) * 128);
        const uint2* wz = Wz0 + kk * 32;
        const uint2* wr = Wr0 + kk * 32;
        mma16(z0, av, wz[0]); mma16(z1, av, wz[2048]);
        mma16(r0, av, wr[0]); mma16(r1, av, wr[2048]);
    }
}
// 16-step k-quarter GEMM, 2 accumulators.
__device__ __forceinline__ void kloop2(const uint4* __restrict__ Ag,
                                       const uint2* __restrict__ W0,
                                       float* a0, float* a1) {
    uint4 abuf[4];
    #pragma unroll
    for (int i = 0; i < 4; i++) abuf[i] = __ldcg(Ag + i * 128);
    #pragma unroll
    for (int kk = 0; kk < 16; kk++) {
        uint4 av = abuf[kk & 3];
        if (kk < 12) abuf[kk & 3] = __ldcg(Ag + (kk + 4) * 128);
        const uint2* w = W0 + kk * 32;
        mma16(a0, av, w[0]);
        mma16(a1, av, w[2048]);
    }
}

// ---------------------------------------------------------------------------
// Input projection (fp16 mma): xg[g][t][b][:] = x[b][t][:] @ W_g^T + b_g
// grid = (48 = gate*16+ny, 512 m-tiles), CTA tile 128x64, 256 threads.
// ---------------------------------------------------------------------------
__global__ __launch_bounds__(256, 2) void proj_kernel(
    const float* __restrict__ x,
    const float* __restrict__ Wz, const float* __restrict__ bz,
    const float* __restrict__ Wr, const float* __restrict__ br,
    const float* __restrict__ Wh, const float* __restrict__ bh)
{
    const int gate = blockIdx.x >> 4;
    const float* __restrict__ W    = (gate == 0) ? Wz : (gate == 1) ? Wr : Wh;
    const float* __restrict__ bias = (gate == 0) ? bz : (gate == 1) ? br : bh;

    __shared__ unsigned As[128][17];   // packed half2 (32 k per chunk = 16 uints)
    __shared__ unsigned Bs[64][17];

    const int tid  = threadIdx.x;
    const int lane = tid & 31;
    const int warp = tid >> 5;
    const int gid  = lane >> 2;
    const int tig  = lane & 3;
    const int wm   = warp >> 1;
    const int wn   = warp & 1;

    const long mbase = (long)blockIdx.y * 128;
    const int  nbase = (blockIdx.x & 15) * 64;

    const int arow  = tid >> 1;
    const int asegf = (tid & 1) * 16;     // float offset within chunk
    const int asegu = (tid & 1) * 8;      // uint offset
    const int brow  = tid >> 3;
    const int bcolf = (tid & 7) * 4;
    const int bcolu = (tid & 7) * 2;

    float acc[2][4][4];
    #pragma unroll
    for (int i = 0; i < 2; i++)
        #pragma unroll
        for (int j = 0; j < 4; j++)
            #pragma unroll
            for (int k = 0; k < 4; k++) acc[i][j][k] = 0.f;

    float4 aR[4], bR[2];
    {
        const float* ap = x + (mbase + arow) * Idim + asegf;
        #pragma unroll
        for (int q = 0; q < 4; q++) aR[q] = reinterpret_cast<const float4*>(ap)[q];
        #pragma unroll
        for (int p = 0; p < 2; p++)
            bR[p] = *reinterpret_cast<const float4*>(W + (long)(nbase + brow + p * 32) * Idim + bcolf);
    }

    for (int kc = 0; kc < Idim; kc += 32) {
        #pragma unroll
        for (int q = 0; q < 4; q++) {
            As[arow][asegu + q * 2 + 0] = packh2(aR[q].x, aR[q].y);
            As[arow][asegu + q * 2 + 1] = packh2(aR[q].z, aR[q].w);
        }
        #pragma unroll
        for (int p = 0; p < 2; p++) {
            Bs[brow + p * 32][bcolu + 0] = packh2(bR[p].x, bR[p].y);
            Bs[brow + p * 32][bcolu + 1] = packh2(bR[p].z, bR[p].w);
        }
        __syncthreads();

        if (kc + 32 < Idim) {
            const float* ap = x + (mbase + arow) * Idim + (kc + 32) + asegf;
            #pragma unroll
            for (int q = 0; q < 4; q++) aR[q] = reinterpret_cast<const float4*>(ap)[q];
            #pragma unroll
            for (int p = 0; p < 2; p++)
                bR[p] = *reinterpret_cast<const float4*>(W + (long)(nbase + brow + p * 32) * Idim + (kc + 32) + bcolf);
        }

        #pragma unroll
        for (int ks = 0; ks < 2; ks++) {   // two k16 fragments per 32-k chunk
            uint4 af[2];
            #pragma unroll
            for (int mt = 0; mt < 2; mt++) {
                int r0 = wm * 32 + mt * 16 + gid;
                af[mt] = make_uint4(As[r0][ks * 8 + tig],     As[r0 + 8][ks * 8 + tig],
                                    As[r0][ks * 8 + 4 + tig], As[r0 + 8][ks * 8 + 4 + tig]);
            }
            #pragma unroll
            for (int nt = 0; nt < 4; nt++) {
                int n0 = wn * 32 + nt * 8 + gid;
                uint2 b = make_uint2(Bs[n0][ks * 8 + tig], Bs[n0][ks * 8 + 4 + tig]);
                mma16(acc[0][nt], af[0], b);
                mma16(acc[1][nt], af[1], b);
            }
        }
        __syncthreads();
    }

    #pragma unroll
    for (int mt = 0; mt < 2; mt++) {
        #pragma unroll
        for (int nt = 0; nt < 4; nt++) {
            #pragma unroll
            for (int i = 0; i < 4; i++) {
                int mr = wm * 32 + mt * 16 + gid + ((i >= 2) ? 8 : 0);
                int j  = nbase + wn * 32 + nt * 8 + tig * 2 + (i & 1);
                long m = mbase + mr;
                int b = (int)(m >> 10);   // x rows are (b, t), t fastest
                int t = (int)(m & 1023);
                float v = acc[mt][nt][i] + bias[j];
                g_xg[(((long)gate * Tdim + t) * Bdim + b) * Hdim + j] = v;
            }
        }
    }
}

// ---------------------------------------------------------------------------
// Persistent scan: 64 CTAs x 512 threads (16 warps = 4 stripes x 4 k-quarters).
// CTA c owns hidden cols [16c, 16c+16).
//   Phase A: wait h-quarter -> fused z+r GEMM (shared A-stream) -> rh publish.
//   Phase B: wait rh-quarter -> h~ GEMM -> update, h publish.
// z and h fp32 live in epilogue-warp registers. State double-buffered by t&1.
// ---------------------------------------------------------------------------
extern __shared__ unsigned char smem_raw[];

__global__ __launch_bounds__(512, 1) void scan_kernel(
    const float* __restrict__ Uz, const float* __restrict__ Ur,
    const float* __restrict__ Uh, const float* __restrict__ h0,
    float* __restrict__ out)
{
    uint2*  WZ   = (uint2*)smem_raw;                      // 32 KB (Uz fragments)
    uint2*  WR   = (uint2*)(smem_raw + 32768);            // 32 KB (Ur fragments)
    uint2*  WH   = (uint2*)(smem_raw + 65536);            // 32 KB (Uh fragments)
    float4* redA = (float4*)(smem_raw + 98304);           // 24 KB z+r k-partials
    float4* redH = (float4*)(smem_raw + 98304 + 24576);   // 12 KB h~ k-partials

    const int c    = blockIdx.x;
    const int tid  = threadIdx.x;
    const int lane = tid & 31;
    const int warp = tid >> 5;
    const int gid  = lane >> 2;
    const int tig  = lane & 3;
    const int s    = warp & 3;     // batch stripe (16 rows)
    const int kq   = warp >> 2;    // k quarter (16 ksteps of 16)

    // ---- one-time: pack weight slices into fp16 B-fragment granules ----
    for (int idx = tid; idx < 2 * 64 * 32; idx += 512) {
        int ln = idx & 31, K = (idx >> 5) & 63, nb = idx >> 11;
        long row = (long)(16 * c + nb * 8 + (ln >> 2)) * Hdim + 16 * K + 2 * (ln & 3);
        const float* rz = Uz + row; WZ[idx] = make_uint2(packh2(rz[0], rz[1]), packh2(rz[8], rz[9]));
        const float* rr = Ur + row; WR[idx] = make_uint2(packh2(rr[0], rr[1]), packh2(rr[8], rr[9]));
        const float* rh = Uh + row; WH[idx] = make_uint2(packh2(rh[0], rh[1]), packh2(rh[8], rh[9]));
    }

    // replay-safe token bases (all flags equal at kernel entry)
    const unsigned baseA = g_flagA[c];
    const unsigned baseH = g_flagH[c];

    const int b0r = s * 16 + gid;          // epilogue row (kq==0 threads)
    const int j0  = 16 * c + 2 * tig;      // epilogue col pair base

    // h fp32 state, register-resident in kq==0 warps; self-init h16 granule.
    float4 h4a, h4b;
    if (kq == 0) {
        h4a = make_float4(h0[b0r * Hdim + j0],       h0[b0r * Hdim + j0 + 1],
                          h0[(b0r + 8) * Hdim + j0], h0[(b0r + 8) * Hdim + j0 + 1]);
        h4b = make_float4(h0[b0r * Hdim + j0 + 8],       h0[b0r * Hdim + j0 + 9],
                          h0[(b0r + 8) * Hdim + j0 + 8], h0[(b0r + 8) * Hdim + j0 + 9]);
        __stcg(&g_h16[1][(c * 4 + s) * 32 + lane],
               make_uint4(packh2(h4a.x, h4a.y), packh2(h4a.z, h4a.w),
                          packh2(h4b.x, h4b.y), packh2(h4b.z, h4b.w)));
    }
    __syncthreads();   // weights + init stores done CTA-wide
    if (tid == 0) strel(&g_flagH[c], baseH + 1);

    for (int t = 0; t < Tdim; t++) {
        const int wpar = t & 1, rpar = (t + 1) & 1;

        // ---- prefetch all epilogue operands (independent of flags) ----
        float2 xz0a, xz0b, xz1a, xz1b, xr0a, xr0b, xr1a, xr1b;
        float2 xh0a, xh0b, xh1a, xh1b;
        if (kq == 0) {
            const float* xzb = g_xg + (long)t * BH;
            const float* xrb = g_xg + ((long)Tdim + t) * BH;
            const float* xhb = g_xg + (2l * Tdim + t) * BH;
            xz0a = __ldcg((const float2*)(xzb + (long)b0r * Hdim + j0));
            xz0b = __ldcg((const float2*)(xzb + (long)(b0r + 8) * Hdim + j0));
            xz1a = __ldcg((const float2*)(xzb + (long)b0r * Hdim + j0 + 8));
            xz1b = __ldcg((const float2*)(xzb + (long)(b0r + 8) * Hdim + j0 + 8));
            xr0a = __ldcg((const float2*)(xrb + (long)b0r * Hdim + j0));
            xr0b = __ldcg((const float2*)(xrb + (long)(b0r + 8) * Hdim + j0));
            xr1a = __ldcg((const float2*)(xrb + (long)b0r * Hdim + j0 + 8));
            xr1b = __ldcg((const float2*)(xrb + (long)(b0r + 8) * Hdim + j0 + 8));
            xh0a = __ldcg((const float2*)(xhb + (long)b0r * Hdim + j0));
            xh0b = __ldcg((const float2*)(xhb + (long)(b0r + 8) * Hdim + j0));
            xh1a = __ldcg((const float2*)(xhb + (long)b0r * Hdim + j0 + 8));
            xh1b = __ldcg((const float2*)(xhb + (long)(b0r + 8) * Hdim + j0 + 8));
        }

        float4 zz0, zz1;   // z gate, register-resident through phase B

        // ================= Phase A: z and r (fused, shared A-stream) =======
        warp_wait(g_flagH, kq, baseH + 1 + t, lane);

        float az0[4] = {0,0,0,0}, az1[4] = {0,0,0,0};
        float ar0[4] = {0,0,0,0}, ar1[4] = {0,0,0,0};
        kloop4(g_h16[rpar] + (kq * 64 + s) * 32 + lane,
               WZ + (kq * 16) * 32 + lane, WR + (kq * 16) * 32 + lane,
               az0, az1, ar0, ar1);

        if (kq > 0) {
            float4* r = redA + (((kq - 1) * 4 + s) * 32 + lane) * 4;
            r[0] = *(float4*)az0; r[1] = *(float4*)az1;
            r[2] = *(float4*)ar0; r[3] = *(float4*)ar1;
        }
        __syncthreads();   // S1
        if (kq == 0) {
            #pragma unroll
            for (int e = 0; e < 3; e++) {
                const float4* r = redA + ((e * 4 + s) * 32 + lane) * 4;
                float4 v0 = r[0], v1 = r[1], v2 = r[2], v3 = r[3];
                az0[0] += v0.x; az0[1] += v0.y; az0[2] += v0.z; az0[3] += v0.w;
                az1[0] += v1.x; az1[1] += v1.y; az1[2] += v1.z; az1[3] += v1.w;
                ar0[0] += v2.x; ar0[1] += v2.y; ar0[2] += v2.z; ar0[3] += v2.w;
                ar1[0] += v3.x; ar1[1] += v3.y; ar1[2] += v3.z; ar1[3] += v3.w;
            }
            zz0 = make_float4(sigf(az0[0] + xz0a.x), sigf(az0[1] + xz0a.y),
                              sigf(az0[2] + xz0b.x), sigf(az0[3] + xz0b.y));
            zz1 = make_float4(sigf(az1[0] + xz1a.x), sigf(az1[1] + xz1a.y),
                              sigf(az1[2] + xz1b.x), sigf(az1[3] + xz1b.y));
            float r00 = sigf(ar0[0] + xr0a.x) * h4a.x, r01 = sigf(ar0[1] + xr0a.y) * h4a.y;
            float r02 = sigf(ar0[2] + xr0b.x) * h4a.z, r03 = sigf(ar0[3] + xr0b.y) * h4a.w;
            float r10 = sigf(ar1[0] + xr1a.x) * h4b.x, r11 = sigf(ar1[1] + xr1a.y) * h4b.y;
            float r12 = sigf(ar1[2] + xr1b.x) * h4b.z, r13 = sigf(ar1[3] + xr1b.y) * h4b.w;
            __stcg(&g_rh16[wpar][(c * 4 + s) * 32 + lane],
                   make_uint4(packh2(r00, r01), packh2(r02, r03),
                              packh2(r10, r11), packh2(r12, r13)));
        }
        __syncthreads();   // S2: all rh stores done
        if (tid == 0) strel(&g_flagA[c], baseA + 1 + t);

        // ================= Phase B: h_tilde + update =======================
        warp_wait(g_flagA, kq, baseA + 1 + t, lane);

        float ab0[4] = {0,0,0,0}, ab1[4] = {0,0,0,0};
        kloop2(g_rh16[wpar] + (kq * 64 + s) * 32 + lane,
               WH + (kq * 16) * 32 + lane, ab0, ab1);

        if (kq > 0) {
            float4* r = redH + (((kq - 1) * 4 + s) * 32 + lane) * 2;
            r[0] = *(float4*)ab0; r[1] = *(float4*)ab1;
        }
        __syncthreads();   // S3
        if (kq == 0) {
            #pragma unroll
            for (int e = 0; e < 3; e++) {
                const float4* r = redH + ((e * 4 + s) * 32 + lane) * 2;
                float4 v0 = r[0], v1 = r[1];
                ab0[0] += v0.x; ab0[1] += v0.y; ab0[2] += v0.z; ab0[3] += v0.w;
                ab1[0] += v1.x; ab1[1] += v1.y; ab1[2] += v1.z; ab1[3] += v1.w;
            }
            float ht00 = tanhf(ab0[0] + xh0a.x), ht01 = tanhf(ab0[1] + xh0a.y);
            float ht02 = tanhf(ab0[2] + xh0b.x), ht03 = tanhf(ab0[3] + xh0b.y);
            float ht10 = tanhf(ab1[0] + xh1a.x), ht11 = tanhf(ab1[1] + xh1a.y);
            float ht12 = tanhf(ab1[2] + xh1b.x), ht13 = tanhf(ab1[3] + xh1b.y);
            float hn00 = fmaf(zz0.x, ht00 - h4a.x, h4a.x);
            float hn01 = fmaf(zz0.y, ht01 - h4a.y, h4a.y);
            float hn02 = fmaf(zz0.z, ht02 - h4a.z, h4a.z);
            float hn03 = fmaf(zz0.w, ht03 - h4a.w, h4a.w);
            float hn10 = fmaf(zz1.x, ht10 - h4b.x, h4b.x);
            float hn11 = fmaf(zz1.y, ht11 - h4b.y, h4b.y);
            float hn12 = fmaf(zz1.z, ht12 - h4b.z, h4b.z);
            float hn13 = fmaf(zz1.w, ht13 - h4b.w, h4b.w);
            h4a = make_float4(hn00, hn01, hn02, hn03);   // state stays in registers
            h4b = make_float4(hn10, hn11, hn12, hn13);
            __stcg(&g_h16[wpar][(c * 4 + s) * 32 + lane],
                   make_uint4(packh2(hn00, hn01), packh2(hn02, hn03),
                              packh2(hn10, hn11), packh2(hn12, hn13)));
            __stcg((float2*)(out + ((long)b0r * Tdim + t) * Hdim + j0),           make_float2(hn00, hn01));
            __stcg((float2*)(out + ((long)(b0r + 8) * Tdim + t) * Hdim + j0),     make_float2(hn02, hn03));
            __stcg((float2*)(out + ((long)b0r * Tdim + t) * Hdim + j0 + 8),       make_float2(hn10, hn11));
            __stcg((float2*)(out + ((long)(b0r + 8) * Tdim + t) * Hdim + j0 + 8), make_float2(hn12, hn13));
            if (t == Tdim - 1) {   // h_n tail
                float* tail = out + (long)Bdim * Tdim * Hdim;
                *(float2*)(tail + b0r * Hdim + j0)           = make_float2(hn00, hn01);
                *(float2*)(tail + (b0r + 8) * Hdim + j0)     = make_float2(hn02, hn03);
                *(float2*)(tail + b0r * Hdim + j0 + 8)       = make_float2(hn10, hn11);
                *(float2*)(tail + (b0r + 8) * Hdim + j0 + 8) = make_float2(hn12, hn13);
            }
        }
        __syncthreads();   // S4: all h stores done
        if (tid == 0) strel(&g_flagH[c], baseH + 2 + t);
    }
}

extern "C" void kernel_launch(void* const* d_in, const int* in_sizes, int n_in,
                              void* d_out, int out_size)
{
    const float* x  = (const float*)d_in[0];
    const float* h0 = (const float*)d_in[1];
    const float* Wz = (const float*)d_in[2];
    const float* bz = (const float*)d_in[3];
    const float* Uz = (const float*)d_in[4];
    const float* Wr = (const float*)d_in[5];
    const float* br = (const float*)d_in[6];
    const float* Ur = (const float*)d_in[7];
    const float* Wh = (const float*)d_in[8];
    const float* bh = (const float*)d_in[9];
    const float* Uh = (const float*)d_in[10];
    float* out = (float*)d_out;

    const int smem_bytes = 98304 + 24576 + 12288;  // 135168 B
    cudaFuncSetAttribute(scan_kernel, cudaFuncAttributeMaxDynamicSharedMemorySize, smem_bytes);

    proj_kernel<<<dim3(48, 512), 256>>>(x, Wz, bz, Wr, br, Wh, bh);
    scan_kernel<<<NCTA, 512, smem_bytes>>>(Uz, Ur, Uh, h0, out);
}

// round 12
// speedup vs baseline: 1.6156x; 1.6156x over previous
#include <cuda_runtime.h>
#include <cuda_fp16.h>

// GRU: B=64, T=1024, INPUT=512, HIDDEN=1024
// out = (B,T,H) fp32 followed by h_n = (1,B,H) fp32.

#define Bdim 64
#define Tdim 1024
#define Idim 512
#define Hdim 1024
#define NCTA 64
#define BH   (Bdim * Hdim)

// ------------------------- device scratch (static; no runtime alloc) -------
static __device__ float g_xg[3ull * Tdim * Bdim * Hdim];  // [gate][t][b][h], bias included
// Double-buffered fragment-ordered fp16 state (granule (K,s): 32 lanes x 16B):
static __device__ uint4 g_h16 [2][64 * 4 * 32];   // h   as mma-A fragments
static __device__ uint4 g_rh16[2][64 * 4 * 32];   // r*h as mma-A fragments
static __device__ unsigned g_bar_count;           // arrivals; self-resets
static __device__ unsigned g_bar_gen;             // monotonic release token

__device__ __forceinline__ unsigned packh2(float a, float b) {
    __half2 h = __floats2half2_rn(a, b);
    return *reinterpret_cast<unsigned*>(&h);
}
__device__ __forceinline__ float sigf(float x) { return 1.0f / (1.0f + __expf(-x)); }

__device__ __forceinline__ unsigned ldacq(const unsigned* p) {
    unsigned v;
    asm volatile("ld.acquire.gpu.global.u32 %0, [%1];" : "=r"(v) : "l"(p));
    return v;
}

// Central split barrier. arrive() must follow a __syncthreads() that orders
// this CTA's stores. One atomicAdd per CTA per barrier; single hot gen line.
__device__ __forceinline__ void bar_arrive() {
    if (threadIdx.x == 0) {
        __threadfence();
        unsigned old = atomicAdd(&g_bar_count, 1u);
        if (old == NCTA - 1) {
            atomicExch(&g_bar_count, 0u);
            __threadfence();
            atomicAdd(&g_bar_gen, 1u);
        }
    }
}
__device__ __forceinline__ void bar_wait(unsigned target) {
    if (threadIdx.x == 0) {
        while ((int)(ldacq(&g_bar_gen) - target) < 0) __nanosleep(64);
    }
    __syncthreads();
}

// D += A(16x16,row) * B(16x8,col)  fp16 -> fp32
__device__ __forceinline__ void mma16(float* d, const uint4 a, const uint2 b) {
    asm volatile(
        "mma.sync.aligned.m16n8k16.row.col.f32.f16.f16.f32 "
        "{%0,%1,%2,%3}, {%4,%5,%6,%7}, {%8,%9}, {%0,%1,%2,%3};\n"
        : "+f"(d[0]), "+f"(d[1]), "+f"(d[2]), "+f"(d[3])
        : "r"(a.x), "r"(a.y), "r"(a.z), "r"(a.w), "r"(b.x), "r"(b.y));
}

// 16-step k-quarter GEMM, 2 accumulators, A streamed from L2 (MLP=4).
__device__ __forceinline__ void kloop2(const uint4* __restrict__ Ag,
                                       const uint2* __restrict__ W0,
                                       float* a0, float* a1) {
    uint4 abuf[4];
    #pragma unroll
    for (int i = 0; i < 4; i++) abuf[i] = __ldcg(Ag + i * 128);
    #pragma unroll
    for (int kk = 0; kk < 16; kk++) {
        uint4 av = abuf[kk & 3];
        if (kk < 12) abuf[kk & 3] = __ldcg(Ag + (kk + 4) * 128);
        const uint2* w = W0 + kk * 32;
        mma16(a0, av, w[0]);
        mma16(a1, av, w[2048]);
    }
}

// ---------------------------------------------------------------------------
// Input projection (fp16 mma): xg[g][t][b][:] = x[b][t][:] @ W_g^T + b_g
// ---------------------------------------------------------------------------
__global__ __launch_bounds__(256, 2) void proj_kernel(
    const float* __restrict__ x,
    const float* __restrict__ Wz, const float* __restrict__ bz,
    const float* __restrict__ Wr, const float* __restrict__ br,
    const float* __restrict__ Wh, const float* __restrict__ bh)
{
    const int gate = blockIdx.x >> 4;
    const float* __restrict__ W    = (gate == 0) ? Wz : (gate == 1) ? Wr : Wh;
    const float* __restrict__ bias = (gate == 0) ? bz : (gate == 1) ? br : bh;

    __shared__ unsigned As[128][17];   // packed half2 (32 k per chunk = 16 uints)
    __shared__ unsigned Bs[64][17];

    const int tid  = threadIdx.x;
    const int lane = tid & 31;
    const int warp = tid >> 5;
    const int gid  = lane >> 2;
    const int tig  = lane & 3;
    const int wm   = warp >> 1;
    const int wn   = warp & 1;

    const long mbase = (long)blockIdx.y * 128;
    const int  nbase = (blockIdx.x & 15) * 64;

    const int arow  = tid >> 1;
    const int asegf = (tid & 1) * 16;
    const int asegu = (tid & 1) * 8;
    const int brow  = tid >> 3;
    const int bcolf = (tid & 7) * 4;
    const int bcolu = (tid & 7) * 2;

    float acc[2][4][4];
    #pragma unroll
    for (int i = 0; i < 2; i++)
        #pragma unroll
        for (int j = 0; j < 4; j++)
            #pragma unroll
            for (int k = 0; k < 4; k++) acc[i][j][k] = 0.f;

    float4 aR[4], bR[2];
    {
        const float* ap = x + (mbase + arow) * Idim + asegf;
        #pragma unroll
        for (int q = 0; q < 4; q++) aR[q] = reinterpret_cast<const float4*>(ap)[q];
        #pragma unroll
        for (int p = 0; p < 2; p++)
            bR[p] = *reinterpret_cast<const float4*>(W + (long)(nbase + brow + p * 32) * Idim + bcolf);
    }

    for (int kc = 0; kc < Idim; kc += 32) {
        #pragma unroll
        for (int q = 0; q < 4; q++) {
            As[arow][asegu + q * 2 + 0] = packh2(aR[q].x, aR[q].y);
            As[arow][asegu + q * 2 + 1] = packh2(aR[q].z, aR[q].w);
        }
        #pragma unroll
        for (int p = 0; p < 2; p++) {
            Bs[brow + p * 32][bcolu + 0] = packh2(bR[p].x, bR[p].y);
            Bs[brow + p * 32][bcolu + 1] = packh2(bR[p].z, bR[p].w);
        }
        __syncthreads();

        if (kc + 32 < Idim) {
            const float* ap = x + (mbase + arow) * Idim + (kc + 32) + asegf;
            #pragma unroll
            for (int q = 0; q < 4; q++) aR[q] = reinterpret_cast<const float4*>(ap)[q];
            #pragma unroll
            for (int p = 0; p < 2; p++)
                bR[p] = *reinterpret_cast<const float4*>(W + (long)(nbase + brow + p * 32) * Idim + (kc + 32) + bcolf);
        }

        #pragma unroll
        for (int ks = 0; ks < 2; ks++) {
            uint4 af[2];
            #pragma unroll
            for (int mt = 0; mt < 2; mt++) {
                int r0 = wm * 32 + mt * 16 + gid;
                af[mt] = make_uint4(As[r0][ks * 8 + tig],     As[r0 + 8][ks * 8 + tig],
                                    As[r0][ks * 8 + 4 + tig], As[r0 + 8][ks * 8 + 4 + tig]);
            }
            #pragma unroll
            for (int nt = 0; nt < 4; nt++) {
                int n0 = wn * 32 + nt * 8 + gid;
                uint2 b = make_uint2(Bs[n0][ks * 8 + tig], Bs[n0][ks * 8 + 4 + tig]);
                mma16(acc[0][nt], af[0], b);
                mma16(acc[1][nt], af[1], b);
            }
        }
        __syncthreads();
    }

    #pragma unroll
    for (int mt = 0; mt < 2; mt++) {
        #pragma unroll
        for (int nt = 0; nt < 4; nt++) {
            #pragma unroll
            for (int i = 0; i < 4; i++) {
                int mr = wm * 32 + mt * 16 + gid + ((i >= 2) ? 8 : 0);
                int j  = nbase + wn * 32 + nt * 8 + tig * 2 + (i & 1);
                long m = mbase + mr;
                int b = (int)(m >> 10);   // x rows are (b, t), t fastest
                int t = (int)(m & 1023);
                float v = acc[mt][nt][i] + bias[j];
                g_xg[(((long)gate * Tdim + t) * Bdim + b) * Hdim + j] = v;
            }
        }
    }
}

// ---------------------------------------------------------------------------
// Persistent scan: 64 CTAs x 512 threads (16 warps = 4 stripes x 4 k-quarters).
// CTA c owns hidden cols [16c, 16c+16).
//   r GEMM -> publish rh -> arrive(A) -> z GEMM (hides barrier A latency)
//   -> wait(A) -> h~ GEMM -> update/publish h -> arrive(B)
//   -> next-step prefetch -> wait(B).
// z and h fp32 live in epilogue-warp registers. State double-buffered by t&1.
// ---------------------------------------------------------------------------
extern __shared__ unsigned char smem_raw[];

__global__ __launch_bounds__(512, 1) void scan_kernel(
    const float* __restrict__ Uz, const float* __restrict__ Ur,
    const float* __restrict__ Uh, const float* __restrict__ h0,
    float* __restrict__ out)
{
    uint2*  WZ   = (uint2*)smem_raw;                      // 32 KB (Uz fragments)
    uint2*  WR   = (uint2*)(smem_raw + 32768);            // 32 KB (Ur fragments)
    uint2*  WH   = (uint2*)(smem_raw + 65536);            // 32 KB (Uh fragments)
    float4* redR = (float4*)(smem_raw + 98304);           // 12 KB r  k-partials
    float4* redZ = (float4*)(smem_raw + 98304 + 12288);   // 12 KB z  k-partials
    float4* redH = (float4*)(smem_raw + 98304 + 24576);   // 12 KB h~ k-partials

    const int c    = blockIdx.x;
    const int tid  = threadIdx.x;
    const int lane = tid & 31;
    const int warp = tid >> 5;
    const int gid  = lane >> 2;
    const int tig  = lane & 3;
    const int s    = warp & 3;     // batch stripe (16 rows)
    const int kq   = warp >> 2;    // k quarter (16 ksteps of 16)

    // ---- one-time: pack weight slices into fp16 B-fragment granules ----
    for (int idx = tid; idx < 2 * 64 * 32; idx += 512) {
        int ln = idx & 31, K = (idx >> 5) & 63, nb = idx >> 11;
        long row = (long)(16 * c + nb * 8 + (ln >> 2)) * Hdim + 16 * K + 2 * (ln & 3);
        const float* rz = Uz + row; WZ[idx] = make_uint2(packh2(rz[0], rz[1]), packh2(rz[8], rz[9]));
        const float* rr = Ur + row; WR[idx] = make_uint2(packh2(rr[0], rr[1]), packh2(rr[8], rr[9]));
        const float* rh = Uh + row; WH[idx] = make_uint2(packh2(rh[0], rh[1]), packh2(rh[8], rh[9]));
    }

    // replay-safe token base: every CTA reads before its own first arrival,
    // and the first gen bump needs all NCTA arrivals.
    const unsigned base = ldacq(&g_bar_gen);

    const int b0r = s * 16 + gid;          // epilogue row (kq==0 threads)
    const int j0  = 16 * c + 2 * tig;      // epilogue col pair base

    // h fp32 state, register-resident in kq==0 warps; self-init h16 granule.
    float4 h4a, h4b;
    if (kq == 0) {
        h4a = make_float4(h0[b0r * Hdim + j0],       h0[b0r * Hdim + j0 + 1],
                          h0[(b0r + 8) * Hdim + j0], h0[(b0r + 8) * Hdim + j0 + 1]);
        h4b = make_float4(h0[b0r * Hdim + j0 + 8],       h0[b0r * Hdim + j0 + 9],
                          h0[(b0r + 8) * Hdim + j0 + 8], h0[(b0r + 8) * Hdim + j0 + 9]);
        __stcg(&g_h16[1][(c * 4 + s) * 32 + lane],
               make_uint4(packh2(h4a.x, h4a.y), packh2(h4a.z, h4a.w),
                          packh2(h4b.x, h4b.y), packh2(h4b.z, h4b.w)));
    }
    __syncthreads();        // weights + init stores done CTA-wide
    bar_arrive();           // init barrier: gen -> base+1
    unsigned tgt = base + 1;

    for (int t = 0; t < Tdim; t++) {
        const int wpar = t & 1, rpar = (t + 1) & 1;

        // ---- prefetch all epilogue operands (before the wait) ----
        float2 xz0a, xz0b, xz1a, xz1b, xr0a, xr0b, xr1a, xr1b;
        float2 xh0a, xh0b, xh1a, xh1b;
        if (kq == 0) {
            const float* xzb = g_xg + (long)t * BH;
            const float* xrb = g_xg + ((long)Tdim + t) * BH;
            const float* xhb = g_xg + (2l * Tdim + t) * BH;
            xz0a = __ldcg((const float2*)(xzb + (long)b0r * Hdim + j0));
            xz0b = __ldcg((const float2*)(xzb + (long)(b0r + 8) * Hdim + j0));
            xz1a = __ldcg((const float2*)(xzb + (long)b0r * Hdim + j0 + 8));
            xz1b = __ldcg((const float2*)(xzb + (long)(b0r + 8) * Hdim + j0 + 8));
            xr0a = __ldcg((const float2*)(xrb + (long)b0r * Hdim + j0));
            xr0b = __ldcg((const float2*)(xrb + (long)(b0r + 8) * Hdim + j0));
            xr1a = __ldcg((const float2*)(xrb + (long)b0r * Hdim + j0 + 8));
            xr1b = __ldcg((const float2*)(xrb + (long)(b0r + 8) * Hdim + j0 + 8));
            xh0a = __ldcg((const float2*)(xhb + (long)b0r * Hdim + j0));
            xh0b = __ldcg((const float2*)(xhb + (long)(b0r + 8) * Hdim + j0));
            xh1a = __ldcg((const float2*)(xhb + (long)b0r * Hdim + j0 + 8));
            xh1b = __ldcg((const float2*)(xhb + (long)(b0r + 8) * Hdim + j0 + 8));
        }

        bar_wait(tgt);   // h_{t-1} fully published grid-wide

        // ================= r GEMM (critical path) =================
        float ar0[4] = {0,0,0,0}, ar1[4] = {0,0,0,0};
        kloop2(g_h16[rpar] + (kq * 64 + s) * 32 + lane,
               WR + (kq * 16) * 32 + lane, ar0, ar1);

        if (kq > 0) {
            float4* r = redR + (((kq - 1) * 4 + s) * 32 + lane) * 2;
            r[0] = *(float4*)ar0; r[1] = *(float4*)ar1;
        }
        __syncthreads();   // S1
        if (kq == 0) {
            #pragma unroll
            for (int e = 0; e < 3; e++) {
                const float4* r = redR + ((e * 4 + s) * 32 + lane) * 2;
                float4 v0 = r[0], v1 = r[1];
                ar0[0] += v0.x; ar0[1] += v0.y; ar0[2] += v0.z; ar0[3] += v0.w;
                ar1[0] += v1.x; ar1[1] += v1.y; ar1[2] += v1.z; ar1[3] += v1.w;
            }
            float r00 = sigf(ar0[0] + xr0a.x) * h4a.x, r01 = sigf(ar0[1] + xr0a.y) * h4a.y;
            float r02 = sigf(ar0[2] + xr0b.x) * h4a.z, r03 = sigf(ar0[3] + xr0b.y) * h4a.w;
            float r10 = sigf(ar1[0] + xr1a.x) * h4b.x, r11 = sigf(ar1[1] + xr1a.y) * h4b.y;
            float r12 = sigf(ar1[2] + xr1b.x) * h4b.z, r13 = sigf(ar1[3] + xr1b.y) * h4b.w;
            __stcg(&g_rh16[wpar][(c * 4 + s) * 32 + lane],
                   make_uint4(packh2(r00, r01), packh2(r02, r03),
                              packh2(r10, r11), packh2(r12, r13)));
        }
        __syncthreads();   // S2: rh stores done
        bar_arrive(); tgt++;

        // ========== z GEMM (off critical path; hides barrier A) ==========
        float az0[4] = {0,0,0,0}, az1[4] = {0,0,0,0};
        kloop2(g_h16[rpar] + (kq * 64 + s) * 32 + lane,
               WZ + (kq * 16) * 32 + lane, az0, az1);
        if (kq > 0) {
            float4* r = redZ + (((kq - 1) * 4 + s) * 32 + lane) * 2;
            r[0] = *(float4*)az0; r[1] = *(float4*)az1;
        }

        bar_wait(tgt);   // rh fully published; also makes redZ visible (syncthreads)

        // ================= h~ GEMM + update =================
        float ab0[4] = {0,0,0,0}, ab1[4] = {0,0,0,0};
        kloop2(g_rh16[wpar] + (kq * 64 + s) * 32 + lane,
               WH + (kq * 16) * 32 + lane, ab0, ab1);

        if (kq > 0) {
            float4* r = redH + (((kq - 1) * 4 + s) * 32 + lane) * 2;
            r[0] = *(float4*)ab0; r[1] = *(float4*)ab1;
        }
        __syncthreads();   // S4
        if (kq == 0) {
            #pragma unroll
            for (int e = 0; e < 3; e++) {
                const float4* rz = redZ + ((e * 4 + s) * 32 + lane) * 2;
                const float4* rh = redH + ((e * 4 + s) * 32 + lane) * 2;
                float4 z0 = rz[0], z1 = rz[1], b0 = rh[0], b1 = rh[1];
                az0[0] += z0.x; az0[1] += z0.y; az0[2] += z0.z; az0[3] += z0.w;
                az1[0] += z1.x; az1[1] += z1.y; az1[2] += z1.z; az1[3] += z1.w;
                ab0[0] += b0.x; ab0[1] += b0.y; ab0[2] += b0.z; ab0[3] += b0.w;
                ab1[0] += b1.x; ab1[1] += b1.y; ab1[2] += b1.z; ab1[3] += b1.w;
            }
            float z00 = sigf(az0[0] + xz0a.x), z01 = sigf(az0[1] + xz0a.y);
            float z02 = sigf(az0[2] + xz0b.x), z03 = sigf(az0[3] + xz0b.y);
            float z10 = sigf(az1[0] + xz1a.x), z11 = sigf(az1[1] + xz1a.y);
            float z12 = sigf(az1[2] + xz1b.x), z13 = sigf(az1[3] + xz1b.y);
            float ht00 = tanhf(ab0[0] + xh0a.x), ht01 = tanhf(ab0[1] + xh0a.y);
            float ht02 = tanhf(ab0[2] + xh0b.x), ht03 = tanhf(ab0[3] + xh0b.y);
            float ht10 = tanhf(ab1[0] + xh1a.x), ht11 = tanhf(ab1[1] + xh1a.y);
            float ht12 = tanhf(ab1[2] + xh1b.x), ht13 = tanhf(ab1[3] + xh1b.y);
            float hn00 = fmaf(z00, ht00 - h4a.x, h4a.x);
            float hn01 = fmaf(z01, ht01 - h4a.y, h4a.y);
            float hn02 = fmaf(z02, ht02 - h4a.z, h4a.z);
            float hn03 = fmaf(z03, ht03 - h4a.w, h4a.w);
            float hn10 = fmaf(z10, ht10 - h4b.x, h4b.x);
            float hn11 = fmaf(z11, ht11 - h4b.y, h4b.y);
            float hn12 = fmaf(z12, ht12 - h4b.z, h4b.z);
            float hn13 = fmaf(z13, ht13 - h4b.w, h4b.w);
            h4a = make_float4(hn00, hn01, hn02, hn03);   // state stays in registers
            h4b = make_float4(hn10, hn11, hn12, hn13);
            __stcg(&g_h16[wpar][(c * 4 + s) * 32 + lane],
                   make_uint4(packh2(hn00, hn01), packh2(hn02, hn03),
                              packh2(hn10, hn11), packh2(hn12, hn13)));
            __stcg((float2*)(out + ((long)b0r * Tdim + t) * Hdim + j0),           make_float2(hn00, hn01));
            __stcg((float2*)(out + ((long)(b0r + 8) * Tdim + t) * Hdim + j0),     make_float2(hn02, hn03));
            __stcg((float2*)(out + ((long)b0r * Tdim + t) * Hdim + j0 + 8),       make_float2(hn10, hn11));
            __stcg((float2*)(out + ((long)(b0r + 8) * Tdim + t) * Hdim + j0 + 8), make_float2(hn12, hn13));
            if (t == Tdim - 1) {   // h_n tail
                float* tail = out + (long)Bdim * Tdim * Hdim;
                *(float2*)(tail + b0r * Hdim + j0)           = make_float2(hn00, hn01);
                *(float2*)(tail + (b0r + 8) * Hdim + j0)     = make_float2(hn02, hn03);
                *(float2*)(tail + b0r * Hdim + j0 + 8)       = make_float2(hn10, hn11);
                *(float2*)(tail + (b0r + 8) * Hdim + j0 + 8) = make_float2(hn12, hn13);
            }
        }
        __syncthreads();   // S5: h stores done
        bar_arrive(); tgt++;
        // next iteration: prefetch runs before bar_wait(tgt) -> overlap
    }
}

extern "C" void kernel_launch(void* const* d_in, const int* in_sizes, int n_in,
                              void* d_out, int out_size)
{
    const float* x  = (const float*)d_in[0];
    const float* h0 = (const float*)d_in[1];
    const float* Wz = (const float*)d_in[2];
    const float* bz = (const float*)d_in[3];
    const float* Uz = (const float*)d_in[4];
    const float* Wr = (const float*)d_in[5];
    const float* br = (const float*)d_in[6];
    const float* Ur = (const float*)d_in[7];
    const float* Wh = (const float*)d_in[8];
    const float* bh = (const float*)d_in[9];
    const float* Uh = (const float*)d_in[10];
    float* out = (float*)d_out;

    const int smem_bytes = 98304 + 36864;  // 135168 B
    cudaFuncSetAttribute(scan_kernel, cudaFuncAttributeMaxDynamicSharedMemorySize, smem_bytes);

    proj_kernel<<<dim3(48, 512), 256>>>(x, Wz, bz, Wr, br, Wh, bh);
    scan_kernel<<<NCTA, 512, smem_bytes>>>(Uz, Ur, Uh, h0, out);
}

// round 13
// speedup vs baseline: 1.8840x; 1.1661x over previous
#include <cuda_runtime.h>
#include <cuda_fp16.h>

// GRU: B=64, T=1024, INPUT=512, HIDDEN=1024
// out = (B,T,H) fp32 followed by h_n = (1,B,H) fp32.

#define Bdim 64
#define Tdim 1024
#define Idim 512
#define Hdim 1024
#define NCTA 64
#define BH   (Bdim * Hdim)

// ------------------------- device scratch (static; no runtime alloc) -------
static __device__ float g_xg[3ull * Tdim * Bdim * Hdim];  // [gate][t][b][h], bias included
// Double-buffered fragment-ordered fp16 state (granule (K,s): 32 lanes x 16B):
static __device__ uint4 g_h16 [2][64 * 4 * 32];   // h   as mma-A fragments
static __device__ uint4 g_rh16[2][64 * 4 * 32];   // r*h as mma-A fragments
// Per-quarter monotonic dataflow counters (padded to 128B lines; index q*32).
// Producers of quarter q = CTAs [16q, 16q+16). Zeroed by proj block (0,0).
static __device__ unsigned g_cntA[128];           // rh published
static __device__ unsigned g_cntH[128];           // h published

__device__ __forceinline__ unsigned packh2(float a, float b) {
    __half2 h = __floats2half2_rn(a, b);
    return *reinterpret_cast<unsigned*>(&h);
}
__device__ __forceinline__ float sigf(float x) { return 1.0f / (1.0f + __expf(-x)); }

__device__ __forceinline__ unsigned ldacq(const unsigned* p) {
    unsigned v;
    asm volatile("ld.acquire.gpu.global.u32 %0, [%1];" : "=r"(v) : "l"(p));
    return v;
}
// Release-publish one arrival (call from thread0 after a __syncthreads that
// orders this CTA's global stores).
__device__ __forceinline__ void cnt_arrive(unsigned* p) {
    __threadfence();
    atomicAdd(p, 1u);
}
// Quarter wait: warp (kq, s==0) lane0 polls its quarter counter; named barrier
// (id 1+kq, 4 warps = 128 threads) releases the 3 sibling warps.
#define NBAR(id) asm volatile("bar.sync %0, 128;" :: "r"(id) : "memory")
__device__ __forceinline__ void quarter_wait(const unsigned* p, unsigned target,
                                             int s, int kq, int lane) {
    if (s == 0) {
        if (lane == 0) {
            while ((int)(ldacq(p) - target) < 0) __nanosleep(40);
        }
        __syncwarp();
    }
    NBAR(1 + kq);
}

// D += A(16x16,row) * B(16x8,col)  fp16 -> fp32
__device__ __forceinline__ void mma16(float* d, const uint4 a, const uint2 b) {
    asm volatile(
        "mma.sync.aligned.m16n8k16.row.col.f32.f16.f16.f32 "
        "{%0,%1,%2,%3}, {%4,%5,%6,%7}, {%8,%9}, {%0,%1,%2,%3};\n"
        : "+f"(d[0]), "+f"(d[1]), "+f"(d[2]), "+f"(d[3])
        : "r"(a.x), "r"(a.y), "r"(a.z), "r"(a.w), "r"(b.x), "r"(b.y));
}

// 16-step k-quarter GEMM, 2 accumulators, A streamed from L2 (MLP=4).
__device__ __forceinline__ void kloop2(const uint4* __restrict__ Ag,
                                       const uint2* __restrict__ W0,
                                       float* a0, float* a1) {
    uint4 abuf[4];
    #pragma unroll
    for (int i = 0; i < 4; i++) abuf[i] = __ldcg(Ag + i * 128);
    #pragma unroll
    for (int kk = 0; kk < 16; kk++) {
        uint4 av = abuf[kk & 3];
        if (kk < 12) abuf[kk & 3] = __ldcg(Ag + (kk + 4) * 128);
        const uint2* w = W0 + kk * 32;
        mma16(a0, av, w[0]);
        mma16(a1, av, w[2048]);
    }
}

// ---------------------------------------------------------------------------
// Input projection (fp16 mma): xg[g][t][b][:] = x[b][t][:] @ W_g^T + b_g
// Block (0,0) also zeroes the scan's dataflow counters (replay-safe reset).
// ---------------------------------------------------------------------------
__global__ __launch_bounds__(256, 2) void proj_kernel(
    const float* __restrict__ x,
    const float* __restrict__ Wz, const float* __restrict__ bz,
    const float* __restrict__ Wr, const float* __restrict__ br,
    const float* __restrict__ Wh, const float* __restrict__ bh)
{
    const int gate = blockIdx.x >> 4;
    const float* __restrict__ W    = (gate == 0) ? Wz : (gate == 1) ? Wr : Wh;
    const float* __restrict__ bias = (gate == 0) ? bz : (gate == 1) ? br : bh;

    if (blockIdx.x == 0 && blockIdx.y == 0 && threadIdx.x < 4) {
        g_cntA[threadIdx.x * 32] = 0;
        g_cntH[threadIdx.x * 32] = 0;
    }

    __shared__ unsigned As[128][17];   // packed half2 (32 k per chunk = 16 uints)
    __shared__ unsigned Bs[64][17];

    const int tid  = threadIdx.x;
    const int lane = tid & 31;
    const int warp = tid >> 5;
    const int gid  = lane >> 2;
    const int tig  = lane & 3;
    const int wm   = warp >> 1;
    const int wn   = warp & 1;

    const long mbase = (long)blockIdx.y * 128;
    const int  nbase = (blockIdx.x & 15) * 64;

    const int arow  = tid >> 1;
    const int asegf = (tid & 1) * 16;
    const int asegu = (tid & 1) * 8;
    const int brow  = tid >> 3;
    const int bcolf = (tid & 7) * 4;
    const int bcolu = (tid & 7) * 2;

    float acc[2][4][4];
    #pragma unroll
    for (int i = 0; i < 2; i++)
        #pragma unroll
        for (int j = 0; j < 4; j++)
            #pragma unroll
            for (int k = 0; k < 4; k++) acc[i][j][k] = 0.f;

    float4 aR[4], bR[2];
    {
        const float* ap = x + (mbase + arow) * Idim + asegf;
        #pragma unroll
        for (int q = 0; q < 4; q++) aR[q] = reinterpret_cast<const float4*>(ap)[q];
        #pragma unroll
        for (int p = 0; p < 2; p++)
            bR[p] = *reinterpret_cast<const float4*>(W + (long)(nbase + brow + p * 32) * Idim + bcolf);
    }

    for (int kc = 0; kc < Idim; kc += 32) {
        #pragma unroll
        for (int q = 0; q < 4; q++) {
            As[arow][asegu + q * 2 + 0] = packh2(aR[q].x, aR[q].y);
            As[arow][asegu + q * 2 + 1] = packh2(aR[q].z, aR[q].w);
        }
        #pragma unroll
        for (int p = 0; p < 2; p++) {
            Bs[brow + p * 32][bcolu + 0] = packh2(bR[p].x, bR[p].y);
            Bs[brow + p * 32][bcolu + 1] = packh2(bR[p].z, bR[p].w);
        }
        __syncthreads();

        if (kc + 32 < Idim) {
            const float* ap = x + (mbase + arow) * Idim + (kc + 32) + asegf;
            #pragma unroll
            for (int q = 0; q < 4; q++) aR[q] = reinterpret_cast<const float4*>(ap)[q];
            #pragma unroll
            for (int p = 0; p < 2; p++)
                bR[p] = *reinterpret_cast<const float4*>(W + (long)(nbase + brow + p * 32) * Idim + (kc + 32) + bcolf);
        }

        #pragma unroll
        for (int ks = 0; ks < 2; ks++) {
            uint4 af[2];
            #pragma unroll
            for (int mt = 0; mt < 2; mt++) {
                int r0 = wm * 32 + mt * 16 + gid;
                af[mt] = make_uint4(As[r0][ks * 8 + tig],     As[r0 + 8][ks * 8 + tig],
                                    As[r0][ks * 8 + 4 + tig], As[r0 + 8][ks * 8 + 4 + tig]);
            }
            #pragma unroll
            for (int nt = 0; nt < 4; nt++) {
                int n0 = wn * 32 + nt * 8 + gid;
                uint2 b = make_uint2(Bs[n0][ks * 8 + tig], Bs[n0][ks * 8 + 4 + tig]);
                mma16(acc[0][nt], af[0], b);
                mma16(acc[1][nt], af[1], b);
            }
        }
        __syncthreads();
    }

    #pragma unroll
    for (int mt = 0; mt < 2; mt++) {
        #pragma unroll
        for (int nt = 0; nt < 4; nt++) {
            #pragma unroll
            for (int i = 0; i < 4; i++) {
                int mr = wm * 32 + mt * 16 + gid + ((i >= 2) ? 8 : 0);
                int j  = nbase + wn * 32 + nt * 8 + tig * 2 + (i & 1);
                long m = mbase + mr;
                int b = (int)(m >> 10);   // x rows are (b, t), t fastest
                int t = (int)(m & 1023);
                float v = acc[mt][nt][i] + bias[j];
                g_xg[(((long)gate * Tdim + t) * Bdim + b) * Hdim + j] = v;
            }
        }
    }
}

// ---------------------------------------------------------------------------
// Persistent scan: 64 CTAs x 512 threads (16 warps = 4 stripes x 4 k-quarters).
// CTA c owns hidden cols [16c, 16c+16).
//   quarter-wait(h) -> r GEMM -> publish rh, cntA arrive
//   -> z GEMM (hides rh handoff) -> quarter-wait(rh) -> h~ GEMM
//   -> update/publish h, cntH arrive -> next-step prefetch.
// Per-quarter counters: wait gates on 16 producers, not all 64 CTAs.
// z and h fp32 live in epilogue-warp registers. State double-buffered by t&1.
// ---------------------------------------------------------------------------
extern __shared__ unsigned char smem_raw[];

__global__ __launch_bounds__(512, 1) void scan_kernel(
    const float* __restrict__ Uz, const float* __restrict__ Ur,
    const float* __restrict__ Uh, const float* __restrict__ h0,
    float* __restrict__ out)
{
    uint2*  WZ   = (uint2*)smem_raw;                      // 32 KB (Uz fragments)
    uint2*  WR   = (uint2*)(smem_raw + 32768);            // 32 KB (Ur fragments)
    uint2*  WH   = (uint2*)(smem_raw + 65536);            // 32 KB (Uh fragments)
    float4* redR = (float4*)(smem_raw + 98304);           // 12 KB r  k-partials
    float4* redZ = (float4*)(smem_raw + 98304 + 12288);   // 12 KB z  k-partials
    float4* redH = (float4*)(smem_raw + 98304 + 24576);   // 12 KB h~ k-partials

    const int c    = blockIdx.x;
    const int tid  = threadIdx.x;
    const int lane = tid & 31;
    const int warp = tid >> 5;
    const int gid  = lane >> 2;
    const int tig  = lane & 3;
    const int s    = warp & 3;     // batch stripe (16 rows)
    const int kq   = warp >> 2;    // k quarter (16 ksteps of 16)
    const int myq  = c >> 4;       // quarter this CTA produces

    // ---- one-time: pack weight slices into fp16 B-fragment granules ----
    for (int idx = tid; idx < 2 * 64 * 32; idx += 512) {
        int ln = idx & 31, K = (idx >> 5) & 63, nb = idx >> 11;
        long row = (long)(16 * c + nb * 8 + (ln >> 2)) * Hdim + 16 * K + 2 * (ln & 3);
        const float* rz = Uz + row; WZ[idx] = make_uint2(packh2(rz[0], rz[1]), packh2(rz[8], rz[9]));
        const float* rr = Ur + row; WR[idx] = make_uint2(packh2(rr[0], rr[1]), packh2(rr[8], rr[9]));
        const float* rh = Uh + row; WH[idx] = make_uint2(packh2(rh[0], rh[1]), packh2(rh[8], rh[9]));
    }

    const int b0r = s * 16 + gid;          // epilogue row (kq==0 threads)
    const int j0  = 16 * c + 2 * tig;      // epilogue col pair base

    // h fp32 state, register-resident in kq==0 warps; self-init h16 granule.
    float4 h4a, h4b;
    if (kq == 0) {
        h4a = make_float4(h0[b0r * Hdim + j0],       h0[b0r * Hdim + j0 + 1],
                          h0[(b0r + 8) * Hdim + j0], h0[(b0r + 8) * Hdim + j0 + 1]);
        h4b = make_float4(h0[b0r * Hdim + j0 + 8],       h0[b0r * Hdim + j0 + 9],
                          h0[(b0r + 8) * Hdim + j0 + 8], h0[(b0r + 8) * Hdim + j0 + 9]);
        __stcg(&g_h16[1][(c * 4 + s) * 32 + lane],
               make_uint4(packh2(h4a.x, h4a.y), packh2(h4a.z, h4a.w),
                          packh2(h4b.x, h4b.y), packh2(h4b.z, h4b.w)));
    }
    __syncthreads();        // weights + init stores done CTA-wide
    if (tid == 0) cnt_arrive(&g_cntH[myq * 32]);   // init h publish

    for (int t = 0; t < Tdim; t++) {
        const int wpar = t & 1, rpar = (t + 1) & 1;
        const unsigned tgt = 16u * (unsigned)(t + 1);

        // ---- prefetch all epilogue operands (before the wait) ----
        float2 xz0a, xz0b, xz1a, xz1b, xr0a, xr0b, xr1a, xr1b;
        float2 xh0a, xh0b, xh1a, xh1b;
        if (kq == 0) {
            const float* xzb = g_xg + (long)t * BH;
            const float* xrb = g_xg + ((long)Tdim + t) * BH;
            const float* xhb = g_xg + (2l * Tdim + t) * BH;
            xz0a = __ldcg((const float2*)(xzb + (long)b0r * Hdim + j0));
            xz0b = __ldcg((const float2*)(xzb + (long)(b0r + 8) * Hdim + j0));
            xz1a = __ldcg((const float2*)(xzb + (long)b0r * Hdim + j0 + 8));
            xz1b = __ldcg((const float2*)(xzb + (long)(b0r + 8) * Hdim + j0 + 8));
            xr0a = __ldcg((const float2*)(xrb + (long)b0r * Hdim + j0));
            xr0b = __ldcg((const float2*)(xrb + (long)(b0r + 8) * Hdim + j0));
            xr1a = __ldcg((const float2*)(xrb + (long)b0r * Hdim + j0 + 8));
            xr1b = __ldcg((const float2*)(xrb + (long)(b0r + 8) * Hdim + j0 + 8));
            xh0a = __ldcg((const float2*)(xhb + (long)b0r * Hdim + j0));
            xh0b = __ldcg((const float2*)(xhb + (long)(b0r + 8) * Hdim + j0));
            xh1a = __ldcg((const float2*)(xhb + (long)b0r * Hdim + j0 + 8));
            xh1b = __ldcg((const float2*)(xhb + (long)(b0r + 8) * Hdim + j0 + 8));
        }

        // h_{t-1} quarter ready (16 producers, one padded counter line)
        quarter_wait(&g_cntH[kq * 32], tgt, s, kq, lane);

        // ================= r GEMM (critical path) =================
        float ar0[4] = {0,0,0,0}, ar1[4] = {0,0,0,0};
        kloop2(g_h16[rpar] + (kq * 64 + s) * 32 + lane,
               WR + (kq * 16) * 32 + lane, ar0, ar1);

        if (kq > 0) {
            float4* r = redR + (((kq - 1) * 4 + s) * 32 + lane) * 2;
            r[0] = *(float4*)ar0; r[1] = *(float4*)ar1;
        }
        __syncthreads();   // S1
        if (kq == 0) {
            #pragma unroll
            for (int e = 0; e < 3; e++) {
                const float4* r = redR + ((e * 4 + s) * 32 + lane) * 2;
                float4 v0 = r[0], v1 = r[1];
                ar0[0] += v0.x; ar0[1] += v0.y; ar0[2] += v0.z; ar0[3] += v0.w;
                ar1[0] += v1.x; ar1[1] += v1.y; ar1[2] += v1.z; ar1[3] += v1.w;
            }
            float r00 = sigf(ar0[0] + xr0a.x) * h4a.x, r01 = sigf(ar0[1] + xr0a.y) * h4a.y;
            float r02 = sigf(ar0[2] + xr0b.x) * h4a.z, r03 = sigf(ar0[3] + xr0b.y) * h4a.w;
            float r10 = sigf(ar1[0] + xr1a.x) * h4b.x, r11 = sigf(ar1[1] + xr1a.y) * h4b.y;
            float r12 = sigf(ar1[2] + xr1b.x) * h4b.z, r13 = sigf(ar1[3] + xr1b.y) * h4b.w;
            __stcg(&g_rh16[wpar][(c * 4 + s) * 32 + lane],
                   make_uint4(packh2(r00, r01), packh2(r02, r03),
                              packh2(r10, r11), packh2(r12, r13)));
        }
        __syncthreads();   // S2: rh stores done
        if (tid == 0) cnt_arrive(&g_cntA[myq * 32]);

        // ========== z GEMM (off critical path; hides rh handoff) ==========
        float az0[4] = {0,0,0,0}, az1[4] = {0,0,0,0};
        kloop2(g_h16[rpar] + (kq * 64 + s) * 32 + lane,
               WZ + (kq * 16) * 32 + lane, az0, az1);
        if (kq > 0) {
            float4* r = redZ + (((kq - 1) * 4 + s) * 32 + lane) * 2;
            r[0] = *(float4*)az0; r[1] = *(float4*)az1;
        }

        // rh quarter ready
        quarter_wait(&g_cntA[kq * 32], tgt, s, kq, lane);

        // ================= h~ GEMM + update =================
        float ab0[4] = {0,0,0,0}, ab1[4] = {0,0,0,0};
        kloop2(g_rh16[wpar] + (kq * 64 + s) * 32 + lane,
               WH + (kq * 16) * 32 + lane, ab0, ab1);

        if (kq > 0) {
            float4* r = redH + (((kq - 1) * 4 + s) * 32 + lane) * 2;
            r[0] = *(float4*)ab0; r[1] = *(float4*)ab1;
        }
        __syncthreads();   // S4 (also publishes redZ CTA-wide)
        if (kq == 0) {
            #pragma unroll
            for (int e = 0; e < 3; e++) {
                const float4* rz = redZ + ((e * 4 + s) * 32 + lane) * 2;
                const float4* rh = redH + ((e * 4 + s) * 32 + lane) * 2;
                float4 z0 = rz[0], z1 = rz[1], b0 = rh[0], b1 = rh[1];
                az0[0] += z0.x; az0[1] += z0.y; az0[2] += z0.z; az0[3] += z0.w;
                az1[0] += z1.x; az1[1] += z1.y; az1[2] += z1.z; az1[3] += z1.w;
                ab0[0] += b0.x; ab0[1] += b0.y; ab0[2] += b0.z; ab0[3] += b0.w;
                ab1[0] += b1.x; ab1[1] += b1.y; ab1[2] += b1.z; ab1[3] += b1.w;
            }
            float z00 = sigf(az0[0] + xz0a.x), z01 = sigf(az0[1] + xz0a.y);
            float z02 = sigf(az0[2] + xz0b.x), z03 = sigf(az0[3] + xz0b.y);
            float z10 = sigf(az1[0] + xz1a.x), z11 = sigf(az1[1] + xz1a.y);
            float z12 = sigf(az1[2] + xz1b.x), z13 = sigf(az1[3] + xz1b.y);
            float ht00 = tanhf(ab0[0] + xh0a.x), ht01 = tanhf(ab0[1] + xh0a.y);
            float ht02 = tanhf(ab0[2] + xh0b.x), ht03 = tanhf(ab0[3] + xh0b.y);
            float ht10 = tanhf(ab1[0] + xh1a.x), ht11 = tanhf(ab1[1] + xh1a.y);
            float ht12 = tanhf(ab1[2] + xh1b.x), ht13 = tanhf(ab1[3] + xh1b.y);
            float hn00 = fmaf(z00, ht00 - h4a.x, h4a.x);
            float hn01 = fmaf(z01, ht01 - h4a.y, h4a.y);
            float hn02 = fmaf(z02, ht02 - h4a.z, h4a.z);
            float hn03 = fmaf(z03, ht03 - h4a.w, h4a.w);
            float hn10 = fmaf(z10, ht10 - h4b.x, h4b.x);
            float hn11 = fmaf(z11, ht11 - h4b.y, h4b.y);
            float hn12 = fmaf(z12, ht12 - h4b.z, h4b.z);
            float hn13 = fmaf(z13, ht13 - h4b.w, h4b.w);
            h4a = make_float4(hn00, hn01, hn02, hn03);   // state stays in registers
            h4b = make_float4(hn10, hn11, hn12, hn13);
            __stcg(&g_h16[wpar][(c * 4 + s) * 32 + lane],
                   make_uint4(packh2(hn00, hn01), packh2(hn02, hn03),
                              packh2(hn10, hn11), packh2(hn12, hn13)));
            __stcg((float2*)(out + ((long)b0r * Tdim + t) * Hdim + j0),           make_float2(hn00, hn01));
            __stcg((float2*)(out + ((long)(b0r + 8) * Tdim + t) * Hdim + j0),     make_float2(hn02, hn03));
            __stcg((float2*)(out + ((long)b0r * Tdim + t) * Hdim + j0 + 8),       make_float2(hn10, hn11));
            __stcg((float2*)(out + ((long)(b0r + 8) * Tdim + t) * Hdim + j0 + 8), make_float2(hn12, hn13));
            if (t == Tdim - 1) {   // h_n tail
                float* tail = out + (long)Bdim * Tdim * Hdim;
                *(float2*)(tail + b0r * Hdim + j0)           = make_float2(hn00, hn01);
                *(float2*)(tail + (b0r + 8) * Hdim + j0)     = make_float2(hn02, hn03);
                *(float2*)(tail + b0r * Hdim + j0 + 8)       = make_float2(hn10, hn11);
                *(float2*)(tail + (b0r + 8) * Hdim + j0 + 8) = make_float2(hn12, hn13);
            }
        }
        __syncthreads();   // S5: h stores done
        if (tid == 0) cnt_arrive(&g_cntH[myq * 32]);
        // next iteration: xg prefetch runs before the quarter wait -> overlap
    }
}

extern "C" void kernel_launch(void* const* d_in, const int* in_sizes, int n_in,
                              void* d_out, int out_size)
{
    const float* x  = (const float*)d_in[0];
    const float* h0 = (const float*)d_in[1];
    const float* Wz = (const float*)d_in[2];
    const float* bz = (const float*)d_in[3];
    const float* Uz = (const float*)d_in[4];
    const float* Wr = (const float*)d_in[5];
    const float* br = (const float*)d_in[6];
    const float* Ur = (const float*)d_in[7];
    const float* Wh = (const float*)d_in[8];
    const float* bh = (const float*)d_in[9];
    const float* Uh = (const float*)d_in[10];
    float* out = (float*)d_out;

    const int smem_bytes = 98304 + 36864;  // 135168 B
    cudaFuncSetAttribute(scan_kernel, cudaFuncAttributeMaxDynamicSharedMemorySize, smem_bytes);

    proj_kernel<<<dim3(48, 512), 256>>>(x, Wz, bz, Wr, br, Wh, bh);
    scan_kernel<<<NCTA, 512, smem_bytes>>>(Uz, Ur, Uh, h0, out);
}